// round 12
// baseline (speedup 1.0000x reference)
#include <cuda_runtime.h>

#define BB 256
#define TT 2048
#define VV 128
#define CC 512
#define KK 10
#define CHUNK 256   // rows of onehots per block in k_w

// scratch (no device allocs allowed)
__device__ float g_alpha[BB * KK];
__device__ float g_beta[BB * KK];
__device__ float g_kappa[BB * KK];

// -------- Kernel 1: params GEMM, one warp per (b, j); also zeroes w --------
// Inline zeroing is deliberate: a separate cudaMemsetAsync graph node costs
// ~2us of serialized stream time (measured R8/R9) vs ~0 for these stores.
__global__ void k_params(const float* __restrict__ x,
                         const float* __restrict__ kap_old,
                         const float* __restrict__ W,
                         const float* __restrict__ bias,
                         float* __restrict__ out_w,
                         float* __restrict__ out_kappa) {
    const int tid = threadIdx.x;
    const int gtid = blockIdx.x * blockDim.x + tid;

    if (gtid < BB * VV) out_w[gtid] = 0.0f;   // d_out poisoned; atomics target

    const int gw = gtid >> 5;
    const int lane = tid & 31;
    if (gw < BB * 3 * KK) {
        const int b = gw / (3 * KK);
        const int j = gw % (3 * KK);

        const float4* xr = (const float4*)(x + b * CC);
        const float4* wr = (const float4*)(W + j * CC);
        float s = 0.0f;
#pragma unroll
        for (int i = 0; i < 4; i++) {
            const float4 a = xr[i * 32 + lane];
            const float4 v = wr[i * 32 + lane];
            s += a.x * v.x + a.y * v.y + a.z * v.z + a.w * v.w;
        }
#pragma unroll
        for (int o = 16; o; o >>= 1) s += __shfl_down_sync(0xffffffffu, s, o);

        if (lane == 0) {
            const float p = __expf(s + bias[j]);
            if (j < KK) {
                g_alpha[b * KK + j] = p;
            } else if (j < 2 * KK) {
                g_beta[b * KK + (j - KK)] = p;
            } else {
                const int k = j - 2 * KK;
                const float kp = kap_old[b * KK + k] + p;
                g_kappa[b * KK + k] = kp;
                out_kappa[b * KK + k] = kp;
            }
        }
    }
    // PDL: this block's dependent writes (incl. w zeroing) are done.
    __syncthreads();
    cudaTriggerProgrammaticLaunchCompletion();
}

// -------- Kernel 2 (phi + w reduce), PDL-overlapped, barrier-free stream ----
// Warp r owns rows [r*32, r*32+32) of the chunk. Lane l computes phi for its
// own row (warp-local, no shared/barrier), the stream loop fetches weights
// via shuffle. Loads are independent of the exp chain -> front-batched under
// MUFU latency. Only the cross-warp reduce epilogue synchronizes.
__global__ void __launch_bounds__(256)
k_w(const float4* __restrict__ oh,
    float* __restrict__ p_out,
    float* __restrict__ w) {
    __shared__ float4 red[8][32];

    const int b = blockIdx.y;
    const int t0 = blockIdx.x * CHUNK;
    const int tid = threadIdx.x;
    const int lane = tid & 31, r = tid >> 5;

    cudaGridDependencySynchronize();   // k_params scratch ready

    // ---- warp-local phi: lane l -> row r*32 + l ----
    const int trow = r * 32 + lane;          // row within chunk
    const float tf = (float)(t0 + trow);
    float myphi = 0.0f;
#pragma unroll
    for (int k = 0; k < KK; k++) {
        const float a  = g_alpha[b * KK + k];
        const float be = g_beta[b * KK + k];
        const float d  = g_kappa[b * KK + k] - tf;
        myphi += a * __expf(-be * d * d);
    }
    __stcs(p_out + b * TT + t0 + trow, myphi);   // coalesced per warp

    // ---- stream 32 rows per warp, weight via shuffle ----
    const float4* wbase = oh + (size_t)(b * TT + t0 + r * 32) * 32;  // 32 f4/row

    float4 acc = make_float4(0.f, 0.f, 0.f, 0.f);
#pragma unroll 8
    for (int i = 0; i < 32; i++) {
        const float4 o = __ldcs(wbase + i * 32 + lane);
        const float ph = __shfl_sync(0xffffffffu, myphi, i);
        acc.x += ph * o.x;
        acc.y += ph * o.y;
        acc.z += ph * o.z;
        acc.w += ph * o.w;
    }

    // ---- cross-warp reduce + atomics ----
    red[r][lane] = acc;
    __syncthreads();
    if (r < 4) {
        const float4 o = red[r + 4][lane];
        acc.x += o.x; acc.y += o.y; acc.z += o.z; acc.w += o.w;
        red[r][lane] = acc;
    }
    __syncthreads();
    if (r == 0) {
        const float4 o1 = red[1][lane], o2 = red[2][lane], o3 = red[3][lane];
        acc.x += o1.x + o2.x + o3.x;
        acc.y += o1.y + o2.y + o3.y;
        acc.z += o1.z + o2.z + o3.z;
        acc.w += o1.w + o2.w + o3.w;
        float* dst = w + b * VV + lane * 4;
        atomicAdd(dst + 0, acc.x);
        atomicAdd(dst + 1, acc.y);
        atomicAdd(dst + 2, acc.z);
        atomicAdd(dst + 3, acc.w);
    }
}

extern "C" void kernel_launch(void* const* d_in, const int* in_sizes, int n_in,
                              void* d_out, int out_size) {
    const float* x        = (const float*)d_in[0];  // (B, C)
    const float* kap_old  = (const float*)d_in[1];  // (B, K)
    const float* onehots  = (const float*)d_in[2];  // (B, T, V)
    const float* W        = (const float*)d_in[3];  // (3K, C)
    const float* bias     = (const float*)d_in[4];  // (3K,)

    float* out   = (float*)d_out;
    float* w_out = out;                       // (B, V)
    float* k_out = out + BB * VV;             // (B, K)
    float* p_out = out + BB * VV + BB * KK;   // (B, T)

    k_params<<<(BB * 3 * KK) / 8, 256>>>(x, kap_old, W, bias, w_out, k_out);

    // PDL: overlap k_w launch/preamble with k_params; device-side
    // cudaGridDependencySynchronize() enforces ordering on scratch.
    cudaLaunchConfig_t cfg = {};
    cfg.gridDim = dim3(TT / CHUNK, BB);
    cfg.blockDim = dim3(256);
    cudaLaunchAttribute attr[1];
    attr[0].id = cudaLaunchAttributeProgrammaticStreamSerialization;
    attr[0].val.programmaticStreamSerializationAllowed = 1;
    cfg.attrs = attr;
    cfg.numAttrs = 1;
    cudaLaunchKernelEx(&cfg, k_w, (const float4*)onehots, p_out, w_out);
}